// round 1
// baseline (speedup 1.0000x reference)
#include <cuda_runtime.h>

// Problem constants (from reference):
//   T=8192, B=512, H=16, IN=1, OUT=5
// Output = FC(GRU hidden states of batch index B-1 only).
#define T_LEN 8192
#define BATCH 512
#define HID   16
#define NOUT  5

// Scratch: hidden state history for the single live batch element.
__device__ float g_hist[T_LEN * HID];

__device__ __forceinline__ float ex2f_(float x) {
    float y; asm("ex2.approx.f32 %0, %1;" : "=f"(y) : "f"(x)); return y;
}
__device__ __forceinline__ float rcpf_(float x) {
    // rcp.approx + 1 Newton iteration (~2^-44 rel err), cheap insurance for
    // 8192-step error accumulation vs the f32 reference.
    float r; asm("rcp.approx.f32 %0, %1;" : "=f"(r) : "f"(x));
    float e = fmaf(-x, r, 1.0f);
    return fmaf(r, e, r);
}

__global__ void __launch_bounds__(32, 1)
gru_seq_kernel(const float* __restrict__ x,
               const float* __restrict__ w_ih,
               const float* __restrict__ w_hh,
               const float* __restrict__ b_ih,
               const float* __restrict__ b_hh)
{
    const unsigned FULL = 0xffffffffu;
    const int lane = threadIdx.x;       // 0..31
    const int j    = lane & 15;         // hidden unit owned by this lane
    const bool low = lane < 16;

    // Lane l<16 handles r-row j; lane l>=16 handles z-row j.
    const int row_rz = low ? j : (HID + j);

    // ---- load per-lane weights into registers ----
    float w_rz[HID];
    #pragma unroll
    for (int k = 0; k < HID; ++k) w_rz[k] = w_hh[row_rz * HID + k];
    const float b_rz   = b_hh[row_rz];
    const float wih_rz = w_ih[row_rz];      // IN == 1
    const float bih_rz = b_ih[row_rz];

    // n-row j: computed redundantly on BOTH lane j and lane j+16
    // (same warp-wide issue cost as splitting, zero shuffles).
    float w_n[HID];
    #pragma unroll
    for (int k = 0; k < HID; ++k) w_n[k] = w_hh[(2 * HID + j) * HID + k];
    const float bhh_n = b_hh[2 * HID + j];
    const float wih_n = w_ih[2 * HID + j];
    const float bih_n = b_ih[2 * HID + j];

    // Replicated hidden state (compile-time indexed registers).
    float h[HID];
    #pragma unroll
    for (int k = 0; k < HID; ++k) h[k] = 0.0f;
    float h_own = 0.0f;   // h[j] for this lane (valid on low lanes)

    // x prefetch: one scalar per lane covers a 32-step chunk; keep 2 chunks in flight.
    const int xoff = BATCH - 1;         // batch index 511, IN=1
    float xv      = x[(0  + lane) * BATCH + xoff];
    float xv_next = x[(32 + lane) * BATCH + xoff];

    const float LOG2E  = 1.4426950408889634f;
    const float LOG2E2 = 2.8853900817779268f;

    const int NCHUNK = T_LEN / 32;
    for (int c = 0; c < NCHUNK; ++c) {
        #pragma unroll 4
        for (int s = 0; s < 32; ++s) {
            const float xt = __shfl_sync(FULL, xv, s);

            // input-gate contributions (IN = 1)
            const float xg_rz = fmaf(xt, wih_rz, bih_rz);
            const float xg_n  = fmaf(xt, wih_n,  bih_n);

            // hg_rz = w_rz . h + b_rz   (4 accumulators -> short chain)
            float a0 = b_rz, a1 = 0.f, a2 = 0.f, a3 = 0.f;
            // hg_n  = w_n  . h + bhh_n
            float c0 = bhh_n, c1 = 0.f, c2 = 0.f, c3 = 0.f;
            #pragma unroll
            for (int k = 0; k < HID; k += 4) {
                a0 = fmaf(w_rz[k    ], h[k    ], a0);
                a1 = fmaf(w_rz[k + 1], h[k + 1], a1);
                a2 = fmaf(w_rz[k + 2], h[k + 2], a2);
                a3 = fmaf(w_rz[k + 3], h[k + 3], a3);
                c0 = fmaf(w_n [k    ], h[k    ], c0);
                c1 = fmaf(w_n [k + 1], h[k + 1], c1);
                c2 = fmaf(w_n [k + 2], h[k + 2], c2);
                c3 = fmaf(w_n [k + 3], h[k + 3], c3);
            }
            const float hg_rz = (a0 + a1) + (a2 + a3);
            const float hg_n  = (c0 + c1) + (c2 + c3);

            // one warp-wide sigmoid: low lanes -> r[j], high lanes -> z[j]
            const float garg = xg_rz + hg_rz;
            const float g    = rcpf_(1.0f + ex2f_(-LOG2E * garg));
            const float z    = __shfl_xor_sync(FULL, g, 16);  // low lanes: z[j]

            // n = tanh(xg_n + r * hg_n)  via  1 - 2/(e^{2v}+1)
            const float narg = fmaf(g, hg_n, xg_n);           // g == r on low lanes
            const float e2   = ex2f_(narg * LOG2E2);
            const float n    = fmaf(-2.0f, rcpf_(e2 + 1.0f), 1.0f);

            // h_new = z*h + (1-z)*n = n + z*(h-n)
            const float hn = fmaf(z, h_own - n, n);
            h_own = hn;

            // broadcast new hidden state to all lanes (valid source lanes 0..15)
            #pragma unroll
            for (int k = 0; k < HID; ++k) h[k] = __shfl_sync(FULL, hn, k);

            if (low) g_hist[(c * 32 + s) * HID + j] = hn;
        }
        xv = xv_next;
        const int nc = c + 2;
        if (nc < NCHUNK) xv_next = x[(nc * 32 + lane) * BATCH + xoff];
    }
}

// out[t][o] = h_t . fc_w[o] + fc_b[o]   — trivially parallel, ~microseconds.
__global__ void fc_kernel(const float* __restrict__ fc_w,
                          const float* __restrict__ fc_b,
                          float* __restrict__ out)
{
    const int i = blockIdx.x * blockDim.x + threadIdx.x;
    if (i >= T_LEN * NOUT) return;
    const int t = i / NOUT;
    const int o = i - t * NOUT;
    const float* hrow = &g_hist[t * HID];
    float acc = fc_b[o];
    #pragma unroll
    for (int k = 0; k < HID; ++k)
        acc = fmaf(hrow[k], fc_w[o * HID + k], acc);
    out[i] = acc;
}

extern "C" void kernel_launch(void* const* d_in, const int* in_sizes, int n_in,
                              void* d_out, int out_size)
{
    const float* x    = (const float*)d_in[0];
    const float* w_ih = (const float*)d_in[1];
    const float* w_hh = (const float*)d_in[2];
    const float* b_ih = (const float*)d_in[3];
    const float* b_hh = (const float*)d_in[4];
    const float* fc_w = (const float*)d_in[5];
    const float* fc_b = (const float*)d_in[6];
    float* out = (float*)d_out;

    gru_seq_kernel<<<1, 32>>>(x, w_ih, w_hh, b_ih, b_hh);

    const int n = T_LEN * NOUT;
    fc_kernel<<<(n + 255) / 256, 256>>>(fc_w, fc_b, out);
}

// round 2
// speedup vs baseline: 1.8269x; 1.8269x over previous
#include <cuda_runtime.h>
#include <cstdint>

// T=8192, B=512, H=16, IN=1, OUT=5; output = FC(GRU hidden of batch index 511).
#define T_LEN 8192
#define BATCH 512
#define HID   16
#define NOUT  5

__device__ float g_hist[T_LEN * HID];

__device__ __forceinline__ float tanhap(float x) {
    float y; asm("tanh.approx.f32 %0, %1;" : "=f"(y) : "f"(x)); return y;
}
__device__ __forceinline__ unsigned long long pk2(float lo, float hi) {
    unsigned long long r; asm("mov.b64 %0, {%1, %2};" : "=l"(r) : "f"(lo), "f"(hi)); return r;
}
__device__ __forceinline__ void upk2(float& lo, float& hi, unsigned long long v) {
    asm("mov.b64 {%0, %1}, %2;" : "=f"(lo), "=f"(hi) : "l"(v));
}
__device__ __forceinline__ unsigned long long fma2(unsigned long long a, unsigned long long b,
                                                   unsigned long long c) {
    unsigned long long d;
    asm("fma.rn.f32x2 %0, %1, %2, %3;" : "=l"(d) : "l"(a), "l"(b), "l"(c));
    return d;
}
__device__ __forceinline__ unsigned long long add2(unsigned long long a, unsigned long long b) {
    unsigned long long d;
    asm("add.rn.f32x2 %0, %1, %2;" : "=l"(d) : "l"(a), "l"(b));
    return d;
}

__global__ void __launch_bounds__(32, 1)
gru_seq_kernel(const float* __restrict__ x,
               const float* __restrict__ w_ih,
               const float* __restrict__ w_hh,
               const float* __restrict__ b_ih,
               const float* __restrict__ b_hh)
{
    __shared__ __align__(16) float hbuf[2][16];   // double-buffered hidden state
    const unsigned FULL = 0xffffffffu;
    const int lane = threadIdx.x;
    const int j    = lane & 15;    // hidden unit owned by this lane (halves redundant)

    // ---- per-lane weights, packed f32x2, gates pre-halved for the tanh trick ----
    // sigmoid(v) = 0.5 + 0.5*tanh(v/2): halve r/z rows entirely.
    // n: narg = xg_n + r*hg_n = xg_n + hg_n/2 + tanh(garg_r/2)*(hg_n/2): halve whh_n,bhh_n only.
    unsigned long long wr[8], wz[8], wn[8];
    #pragma unroll
    for (int k = 0; k < 8; ++k) {
        const float* rr = &w_hh[j * HID];
        const float* rz = &w_hh[(HID + j) * HID];
        const float* rn = &w_hh[(2 * HID + j) * HID];
        wr[k] = pk2(0.5f * rr[2 * k], 0.5f * rr[2 * k + 1]);
        wz[k] = pk2(0.5f * rz[2 * k], 0.5f * rz[2 * k + 1]);
        wn[k] = pk2(0.5f * rn[2 * k], 0.5f * rn[2 * k + 1]);
    }
    const float wih_r2 = 0.5f * w_ih[j];
    const float bias_r2 = 0.5f * (b_ih[j] + b_hh[j]);
    const float wih_z2 = 0.5f * w_ih[HID + j];
    const float bias_z2 = 0.5f * (b_ih[HID + j] + b_hh[HID + j]);
    const float wih_n = w_ih[2 * HID + j];
    const float bih_n = b_ih[2 * HID + j];
    const unsigned long long bn2pk = pk2(0.5f * b_hh[2 * HID + j], 0.0f);
    const unsigned long long Z64 = 0ull;

    // init h = 0
    if (lane < 16) { hbuf[0][j] = 0.0f; hbuf[1][j] = 0.0f; }
    __syncwarp();
    float h_own = 0.0f;

    uint32_t sbase;
    asm("{ .reg .u64 t; cvta.to.shared.u64 t, %1; cvt.u32.u64 %0, t; }"
        : "=r"(sbase) : "l"(&hbuf[0][0]));

    // x prefetch: one scalar per lane per 32-step chunk, 2 chunks in flight
    const int xoff = BATCH - 1;
    float xv      = x[(0  + lane) * BATCH + xoff];
    float xv_next = x[(32 + lane) * BATCH + xoff];

    const int NCHUNK = T_LEN / 32;
    for (int c = 0; c < NCHUNK; ++c) {
        #pragma unroll 4
        for (int s = 0; s < 32; ++s) {
            const int p = s & 1;                    // read buffer parity
            const uint32_t raddr = sbase + (uint32_t)(p * 64);

            unsigned long long h0, h1, h2, h3, h4, h5, h6, h7;
            asm volatile("ld.shared.v2.u64 {%0, %1}, [%2];" : "=l"(h0), "=l"(h1) : "r"(raddr));
            asm volatile("ld.shared.v2.u64 {%0, %1}, [%2];" : "=l"(h2), "=l"(h3) : "r"(raddr + 16));
            asm volatile("ld.shared.v2.u64 {%0, %1}, [%2];" : "=l"(h4), "=l"(h5) : "r"(raddr + 32));
            asm volatile("ld.shared.v2.u64 {%0, %1}, [%2];" : "=l"(h6), "=l"(h7) : "r"(raddr + 48));

            const float xt  = __shfl_sync(FULL, xv, s);
            const float xgr = fmaf(xt, wih_r2, bias_r2);
            const float xgz = fmaf(xt, wih_z2, bias_z2);
            const float xgn = fmaf(xt, wih_n,  bih_n);

            // three 16-dots as 24 packed FMAs, 2 accumulator chains each
            unsigned long long ar0, ar1, az0, az1, an0, an1;
            ar0 = fma2(wr[0], h0, Z64);   ar1 = fma2(wr[1], h1, Z64);
            az0 = fma2(wz[0], h0, Z64);   az1 = fma2(wz[1], h1, Z64);
            an0 = fma2(wn[0], h0, bn2pk); an1 = fma2(wn[1], h1, Z64);
            ar0 = fma2(wr[2], h2, ar0);   ar1 = fma2(wr[3], h3, ar1);
            az0 = fma2(wz[2], h2, az0);   az1 = fma2(wz[3], h3, az1);
            an0 = fma2(wn[2], h2, an0);   an1 = fma2(wn[3], h3, an1);
            ar0 = fma2(wr[4], h4, ar0);   ar1 = fma2(wr[5], h5, ar1);
            az0 = fma2(wz[4], h4, az0);   az1 = fma2(wz[5], h5, az1);
            an0 = fma2(wn[4], h4, an0);   an1 = fma2(wn[5], h5, an1);
            ar0 = fma2(wr[6], h6, ar0);   ar1 = fma2(wr[7], h7, ar1);
            az0 = fma2(wz[6], h6, az0);   az1 = fma2(wz[7], h7, az1);
            an0 = fma2(wn[6], h6, an0);   an1 = fma2(wn[7], h7, an1);

            float lo, hi;
            upk2(lo, hi, add2(ar0, ar1)); const float hg_r2 = lo + hi;
            upk2(lo, hi, add2(az0, az1)); const float hg_z2 = lo + hi;
            upk2(lo, hi, add2(an0, an1)); const float hg_n2 = lo + hi;

            const float t_r = tanhap(xgr + hg_r2);          // tanh(garg_r/2)
            const float t_z = tanhap(xgz + hg_z2);          // tanh(garg_z/2)
            const float narg = fmaf(t_r, hg_n2, xgn + hg_n2);
            const float n  = tanhap(narg);
            const float zg = fmaf(0.5f, t_z, 0.5f);
            const float hn = fmaf(zg, h_own - n, n);
            h_own = hn;

            // write next buffer (both halves write identical value -> fine)
            const uint32_t waddr = sbase + (uint32_t)((p ^ 1) * 64) + (uint32_t)(j * 4);
            asm volatile("st.shared.f32 [%0], %1;" :: "r"(waddr), "f"(hn));
            if (lane < 16) g_hist[(c * 32 + s) * HID + j] = hn;
            __syncwarp();
        }
        xv = xv_next;
        if (c + 2 < NCHUNK) xv_next = x[((c + 2) * 32 + lane) * BATCH + xoff];
    }
}

// out[t][o] = h_t . fc_w[o] + fc_b[o]
__global__ void fc_kernel(const float* __restrict__ fc_w,
                          const float* __restrict__ fc_b,
                          float* __restrict__ out)
{
    const int i = blockIdx.x * blockDim.x + threadIdx.x;
    if (i >= T_LEN * NOUT) return;
    const int t = i / NOUT;
    const int o = i - t * NOUT;
    const float* hrow = &g_hist[t * HID];
    float acc = fc_b[o];
    #pragma unroll
    for (int k = 0; k < HID; ++k)
        acc = fmaf(hrow[k], fc_w[o * HID + k], acc);
    out[i] = acc;
}

extern "C" void kernel_launch(void* const* d_in, const int* in_sizes, int n_in,
                              void* d_out, int out_size)
{
    const float* x    = (const float*)d_in[0];
    const float* w_ih = (const float*)d_in[1];
    const float* w_hh = (const float*)d_in[2];
    const float* b_ih = (const float*)d_in[3];
    const float* b_hh = (const float*)d_in[4];
    const float* fc_w = (const float*)d_in[5];
    const float* fc_b = (const float*)d_in[6];
    float* out = (float*)d_out;

    gru_seq_kernel<<<1, 32>>>(x, w_ih, w_hh, b_ih, b_hh);

    const int n = T_LEN * NOUT;
    fc_kernel<<<(n + 255) / 256, 256>>>(fc_w, fc_b, out);
}

// round 3
// speedup vs baseline: 1.8587x; 1.0174x over previous
#include <cuda_runtime.h>
#include <cstdint>

// T=8192, B=512, H=16, IN=1, OUT=5; output = FC(GRU hidden of batch index 511).
#define T_LEN 8192
#define BATCH 512
#define HID   16
#define NOUT  5

__device__ float g_hist[T_LEN * HID];

__device__ __forceinline__ float tanhap(float x) {
    float y; asm("tanh.approx.f32 %0, %1;" : "=f"(y) : "f"(x)); return y;
}
__device__ __forceinline__ unsigned long long pk2(float lo, float hi) {
    unsigned long long r; asm("mov.b64 %0, {%1, %2};" : "=l"(r) : "f"(lo), "f"(hi)); return r;
}
__device__ __forceinline__ void upk2(float& lo, float& hi, unsigned long long v) {
    asm("mov.b64 {%0, %1}, %2;" : "=f"(lo), "=f"(hi) : "l"(v));
}
__device__ __forceinline__ unsigned long long fma2(unsigned long long a, unsigned long long b,
                                                   unsigned long long c) {
    unsigned long long d;
    asm("fma.rn.f32x2 %0, %1, %2, %3;" : "=l"(d) : "l"(a), "l"(b), "l"(c));
    return d;
}
__device__ __forceinline__ unsigned long long add2(unsigned long long a, unsigned long long b) {
    unsigned long long d;
    asm("add.rn.f32x2 %0, %1, %2;" : "=l"(d) : "l"(a), "l"(b));
    return d;
}

__global__ void __launch_bounds__(32, 1)
gru_seq_kernel(const float* __restrict__ x,
               const float* __restrict__ w_ih,
               const float* __restrict__ w_hh,
               const float* __restrict__ b_ih,
               const float* __restrict__ b_hh)
{
    __shared__ __align__(16) float hbuf[2][16];   // double-buffered hidden state
    const unsigned FULL = 0xffffffffu;
    const int lane = threadIdx.x;
    const int j    = lane & 15;

    // sigmoid(v) = 0.5 + 0.5*tanh(v/2): r/z rows pre-halved.
    // n: narg = xg_n + hg_n/2 + tanh(garg_r/2)*(hg_n/2): halve whh_n/bhh_n only.
    unsigned long long wr[8], wz[8], wn[8];
    #pragma unroll
    for (int k = 0; k < 8; ++k) {
        const float* rr = &w_hh[j * HID];
        const float* rz = &w_hh[(HID + j) * HID];
        const float* rn = &w_hh[(2 * HID + j) * HID];
        wr[k] = pk2(0.5f * rr[2 * k], 0.5f * rr[2 * k + 1]);
        wz[k] = pk2(0.5f * rz[2 * k], 0.5f * rz[2 * k + 1]);
        wn[k] = pk2(0.5f * rn[2 * k], 0.5f * rn[2 * k + 1]);
    }
    const float wih_r2  = 0.5f * w_ih[j];
    const float bias_r2 = 0.5f * (b_ih[j] + b_hh[j]);
    const float wih_z2  = 0.5f * w_ih[HID + j];
    const float bias_z2 = 0.5f * (b_ih[HID + j] + b_hh[HID + j]);
    const float wih_n   = w_ih[2 * HID + j];
    const float bih_n   = b_ih[2 * HID + j];
    const unsigned long long bn2pk = pk2(0.5f * b_hh[2 * HID + j], 0.0f);
    const unsigned long long Z64 = 0ull;

    if (lane < 16) { hbuf[0][j] = 0.0f; hbuf[1][j] = 0.0f; }
    __syncwarp();
    float h_own = 0.0f;

    uint32_t sbase;
    asm("{ .reg .u64 t; cvta.to.shared.u64 t, %1; cvt.u32.u64 %0, t; }"
        : "=r"(sbase) : "l"(&hbuf[0][0]));
    const uint32_t r0a = sbase;                       // read buffer 0
    const uint32_t r1a = sbase + 64u;                 // read buffer 1
    const uint32_t w0a = sbase + 64u + (uint32_t)(j * 4);  // write into buf1
    const uint32_t w1a = sbase + (uint32_t)(j * 4);        // write into buf0

    float* hist = &g_hist[j];        // running history pointer (+HID floats/step)
    const bool low = lane < 16;

    const int xoff = BATCH - 1;
    float xv      = x[(0  + lane) * BATCH + xoff];
    float xv_next = x[(32 + lane) * BATCH + xoff];

    // One GRU step. RADDR/WADDR are compile-time-selected parity addresses.
    // Warp-synchronous: the STS at the end of step t and the LDS at the start
    // of step t+1 are same-warp, program-ordered volatile smem ops (in-order
    // smem pipeline) — no __syncwarp needed; the warp never diverges.
#define GRU_STEP(RADDR, WADDR, SIDX)                                           \
    {                                                                          \
        unsigned long long h0, h1, h2, h3, h4, h5, h6, h7;                     \
        asm volatile("ld.shared.v2.u64 {%0, %1}, [%2];"                        \
                     : "=l"(h0), "=l"(h1) : "r"(RADDR));                       \
        asm volatile("ld.shared.v2.u64 {%0, %1}, [%2];"                        \
                     : "=l"(h2), "=l"(h3) : "r"((RADDR) + 16));                \
        asm volatile("ld.shared.v2.u64 {%0, %1}, [%2];"                        \
                     : "=l"(h4), "=l"(h5) : "r"((RADDR) + 32));                \
        asm volatile("ld.shared.v2.u64 {%0, %1}, [%2];"                        \
                     : "=l"(h6), "=l"(h7) : "r"((RADDR) + 48));                \
        const float xt  = __shfl_sync(FULL, xv, (SIDX));                       \
        const float xgr = fmaf(xt, wih_r2, bias_r2);                           \
        const float xgz = fmaf(xt, wih_z2, bias_z2);                           \
        const float xgn = fmaf(xt, wih_n,  bih_n);                             \
        unsigned long long ar0, ar1, az0, az1, an0, an1;                       \
        ar0 = fma2(wr[0], h0, Z64);   ar1 = fma2(wr[1], h1, Z64);              \
        an0 = fma2(wn[0], h0, bn2pk); an1 = fma2(wn[1], h1, Z64);              \
        az0 = fma2(wz[0], h0, Z64);   az1 = fma2(wz[1], h1, Z64);              \
        ar0 = fma2(wr[2], h2, ar0);   ar1 = fma2(wr[3], h3, ar1);              \
        an0 = fma2(wn[2], h2, an0);   an1 = fma2(wn[3], h3, an1);              \
        az0 = fma2(wz[2], h2, az0);   az1 = fma2(wz[3], h3, az1);              \
        ar0 = fma2(wr[4], h4, ar0);   ar1 = fma2(wr[5], h5, ar1);              \
        an0 = fma2(wn[4], h4, an0);   an1 = fma2(wn[5], h5, an1);              \
        az0 = fma2(wz[4], h4, az0);   az1 = fma2(wz[5], h5, az1);              \
        ar0 = fma2(wr[6], h6, ar0);   ar1 = fma2(wr[7], h7, ar1);              \
        an0 = fma2(wn[6], h6, an0);   an1 = fma2(wn[7], h7, an1);              \
        az0 = fma2(wz[6], h6, az0);   az1 = fma2(wz[7], h7, az1);              \
        float lo, hi;                                                          \
        upk2(lo, hi, add2(ar0, ar1)); const float hg_r2 = lo + hi;             \
        upk2(lo, hi, add2(an0, an1)); const float hg_n2 = lo + hi;             \
        upk2(lo, hi, add2(az0, az1)); const float hg_z2 = lo + hi;             \
        const float t_r  = tanhap(xgr + hg_r2);                                \
        const float base = xgn + hg_n2;                                        \
        const float narg = fmaf(t_r, hg_n2, base);                             \
        const float t_z  = tanhap(xgz + hg_z2);                                \
        const float n    = tanhap(narg);                                       \
        const float zg   = fmaf(0.5f, t_z, 0.5f);                              \
        const float hn   = fmaf(zg, h_own - n, n);                             \
        h_own = hn;                                                            \
        asm volatile("st.shared.f32 [%0], %1;" :: "r"(WADDR), "f"(hn));        \
        if (low) *hist = hn;                                                   \
        hist += HID;                                                           \
    }

    const int NCHUNK = T_LEN / 32;
    for (int c = 0; c < NCHUNK; ++c) {
        #pragma unroll 2
        for (int s = 0; s < 32; s += 2) {
            GRU_STEP(r0a, w0a, s);       // read buf0, write buf1
            GRU_STEP(r1a, w1a, s + 1);   // read buf1, write buf0
        }
        xv = xv_next;
        if (c + 2 < NCHUNK) xv_next = x[((c + 2) * 32 + lane) * BATCH + xoff];
    }
#undef GRU_STEP
}

// out[t][o] = h_t . fc_w[o] + fc_b[o]
__global__ void fc_kernel(const float* __restrict__ fc_w,
                          const float* __restrict__ fc_b,
                          float* __restrict__ out)
{
    const int i = blockIdx.x * blockDim.x + threadIdx.x;
    if (i >= T_LEN * NOUT) return;
    const int t = i / NOUT;
    const int o = i - t * NOUT;
    const float* hrow = &g_hist[t * HID];
    float acc = fc_b[o];
    #pragma unroll
    for (int k = 0; k < HID; ++k)
        acc = fmaf(hrow[k], fc_w[o * HID + k], acc);
    out[i] = acc;
}

extern "C" void kernel_launch(void* const* d_in, const int* in_sizes, int n_in,
                              void* d_out, int out_size)
{
    const float* x    = (const float*)d_in[0];
    const float* w_ih = (const float*)d_in[1];
    const float* w_hh = (const float*)d_in[2];
    const float* b_ih = (const float*)d_in[3];
    const float* b_hh = (const float*)d_in[4];
    const float* fc_w = (const float*)d_in[5];
    const float* fc_b = (const float*)d_in[6];
    float* out = (float*)d_out;

    gru_seq_kernel<<<1, 32>>>(x, w_ih, w_hh, b_ih, b_hh);

    const int n = T_LEN * NOUT;
    fc_kernel<<<(n + 255) / 256, 256>>>(fc_w, fc_b, out);
}